// round 2
// baseline (speedup 1.0000x reference)
#include <cuda_runtime.h>
#include <math.h>

#define NN 32768
#define EE 524288
#define BB 64
#define TT 512
#define H  128
#define DD 256
#define RH 256
#define G3 768
#define GRU_BLOCKS 96
#define GRU_THREADS 128

// ---------------- scratch (static device globals; no dynamic alloc) ----------
__device__ __align__(128) float d_hs1[NN * H];
__device__ __align__(128) float d_h1 [NN * H];
__device__ __align__(128) float d_hs2[NN * H];
__device__ __align__(128) float d_h2 [NN * H];
__device__ float d_ss1[NN], d_sd1[NN], d_ss2[NN], d_sd2[NN];
__device__ float d_v1[DD], d_v2[H];
__device__ __align__(128) float d_xg  [(size_t)NN * G3];   // ~100 MB
__device__ __align__(128) float d_hseq[(size_t)NN * RH];   // 32 MB
__device__ __align__(128) float d_hbuf[BB * RH];
__device__ __align__(128) float d_gh  [BB * G3];
__device__ int d_cnt[NN], d_rowptr[NN + 1], d_cursor[NN], d_esrc[EE];
__device__ unsigned d_bar_cnt = 0;
__device__ unsigned d_bar_gen = 0;

// ---------------- init / CSR build ------------------------------------------
__global__ void k_init() {
    int i = blockIdx.x * blockDim.x + threadIdx.x;
    if (i < NN) d_cnt[i] = 0;
    if (i < BB * RH) d_hbuf[i] = 0.f;
}

__global__ void k_count(const int* __restrict__ dst) {
    int e = blockIdx.x * blockDim.x + threadIdx.x;
    if (e < EE) atomicAdd(&d_cnt[dst[e]], 1);
}

__global__ void k_scan() {
    __shared__ int part[1024];
    int tid = threadIdx.x;
    int base = tid * 32;
    int c[32];
    int s = 0;
#pragma unroll
    for (int j = 0; j < 32; ++j) { c[j] = d_cnt[base + j]; s += c[j]; }
    part[tid] = s;
    __syncthreads();
    if (tid == 0) {
        int run = 0;
        for (int i = 0; i < 1024; ++i) { int t = part[i]; part[i] = run; run += t; }
        d_rowptr[NN] = run;
    }
    __syncthreads();
    int off = part[tid];
#pragma unroll
    for (int j = 0; j < 32; ++j) {
        d_rowptr[base + j] = off;
        d_cursor[base + j] = off;
        off += c[j];
    }
}

__global__ void k_scatter(const int* __restrict__ src, const int* __restrict__ dst) {
    int e = blockIdx.x * blockDim.x + threadIdx.x;
    if (e < EE) {
        int p = atomicAdd(&d_cursor[dst[e]], 1);
        d_esrc[p] = src[e];
    }
}

// ---------------- folded dest-score vectors: v = Wdst @ a_dst ----------------
__global__ void k_vdst(const float* __restrict__ W1, const float* __restrict__ a1,
                       const float* __restrict__ W2, const float* __restrict__ a2) {
    int tid = threadIdx.x;
    if (blockIdx.x == 0) {
        if (tid < DD) {
            float s = 0.f;
            for (int j = 0; j < H; ++j) s += W1[tid * H + j] * a1[j];
            d_v1[tid] = s;
        }
    } else {
        if (tid < H) {
            float s = 0.f;
            for (int j = 0; j < H; ++j) s += W2[tid * H + j] * a2[j];
            d_v2[tid] = s;
        }
    }
}

// ---------------- generic tiled fp32 GEMM: C[M,Nc] = A[M,K]@B[K,Nc] (+bias) --
// A may be a concat of (A, A2) along K with split K1 (row strides K1 each).
__global__ void __launch_bounds__(256)
k_gemm(const float* __restrict__ A, const float* __restrict__ A2, int K1,
       int K, int Nc, const float* __restrict__ B, const float* __restrict__ bias,
       float* __restrict__ C) {
    __shared__ float As[16][68];
    __shared__ float Bs[16][64];
    const int bm = blockIdx.y * 64, bn = blockIdx.x * 64;
    const int tid = threadIdx.x;
    const int tc = tid & 15, tr = tid >> 4;
    float acc[4][4] = {};
    for (int k0 = 0; k0 < K; k0 += 16) {
#pragma unroll
        for (int i = tid; i < 64 * 16; i += 256) {
            int m = i >> 4, kk = i & 15;
            int gk = k0 + kk, gm = bm + m;
            float v;
            if (A2) v = (gk < K1) ? A[gm * K1 + gk] : A2[gm * K1 + (gk - K1)];
            else    v = A[(size_t)gm * K + gk];
            As[kk][m] = v;
        }
#pragma unroll
        for (int i = tid; i < 16 * 64; i += 256) {
            int kk = i >> 6, n = i & 63;
            Bs[kk][n] = B[(size_t)(k0 + kk) * Nc + bn + n];
        }
        __syncthreads();
#pragma unroll
        for (int kk = 0; kk < 16; ++kk) {
            float4 av = *(const float4*)&As[kk][tr * 4];
            float4 bv = *(const float4*)&Bs[kk][tc * 4];
            acc[0][0] += av.x * bv.x; acc[0][1] += av.x * bv.y; acc[0][2] += av.x * bv.z; acc[0][3] += av.x * bv.w;
            acc[1][0] += av.y * bv.x; acc[1][1] += av.y * bv.y; acc[1][2] += av.y * bv.z; acc[1][3] += av.y * bv.w;
            acc[2][0] += av.z * bv.x; acc[2][1] += av.z * bv.y; acc[2][2] += av.z * bv.z; acc[2][3] += av.z * bv.w;
            acc[3][0] += av.w * bv.x; acc[3][1] += av.w * bv.y; acc[3][2] += av.w * bv.z; acc[3][3] += av.w * bv.w;
        }
        __syncthreads();
    }
    float b0 = 0, b1 = 0, b2 = 0, b3 = 0;
    if (bias) {
        b0 = bias[bn + tc * 4 + 0]; b1 = bias[bn + tc * 4 + 1];
        b2 = bias[bn + tc * 4 + 2]; b3 = bias[bn + tc * 4 + 3];
    }
#pragma unroll
    for (int i = 0; i < 4; ++i) {
        float4 o;
        o.x = acc[i][0] + b0; o.y = acc[i][1] + b1; o.z = acc[i][2] + b2; o.w = acc[i][3] + b3;
        *(float4*)&C[(size_t)(bm + tr * 4 + i) * Nc + bn + tc * 4] = o;
    }
}

// ---------------- per-node attention scores (two dots per warp) --------------
__global__ void k_scores(const float* __restrict__ A, int KA, const float* __restrict__ av,
                         const float* __restrict__ X, int KX, const float* __restrict__ v,
                         float* __restrict__ ss, float* __restrict__ sd) {
    int lane = threadIdx.x & 31, wrp = threadIdx.x >> 5;
    int n = blockIdx.x * 8 + wrp;
    float p = 0.f;
    for (int k = lane; k < KA; k += 32) p += A[(size_t)n * KA + k] * av[k];
    for (int o = 16; o; o >>= 1) p += __shfl_xor_sync(0xffffffffu, p, o);
    float q = 0.f;
    for (int k = lane; k < KX; k += 32) q += X[(size_t)n * KX + k] * v[k];
    for (int o = 16; o; o >>= 1) q += __shfl_xor_sync(0xffffffffu, q, o);
    if (lane == 0) { ss[n] = p; sd[n] = q; }
}

// ---------------- GAT softmax aggregation (warp per dst node) ----------------
__global__ void k_aggregate(const float* __restrict__ ss, const float* __restrict__ sd,
                            const float* __restrict__ hs, const float* __restrict__ bias,
                            float* __restrict__ out, int do_relu) {
    int lane = threadIdx.x & 31, wrp = threadIdx.x >> 5;
    int n = blockIdx.x * 8 + wrp;
    int beg = d_rowptr[n], end = d_rowptr[n + 1];
    float sdn = sd[n];
    float mx = -1e30f;
    for (int e = beg + lane; e < end; e += 32) {
        float al = ss[d_esrc[e]] + sdn;
        al = al > 0.f ? al : 0.2f * al;
        mx = fmaxf(mx, al);
    }
    for (int o = 16; o; o >>= 1) mx = fmaxf(mx, __shfl_xor_sync(0xffffffffu, mx, o));
    float den = 0.f;
    for (int e = beg + lane; e < end; e += 32) {
        float al = ss[d_esrc[e]] + sdn;
        al = al > 0.f ? al : 0.2f * al;
        den += expf(al - mx);
    }
    for (int o = 16; o; o >>= 1) den += __shfl_xor_sync(0xffffffffu, den, o);
    float inv = 1.f / (den + 1e-16f);
    float a0 = 0.f, a1 = 0.f, a2 = 0.f, a3 = 0.f;
    for (int e = beg; e < end; ++e) {
        int s = d_esrc[e];
        float al = ss[s] + sdn;
        al = al > 0.f ? al : 0.2f * al;
        float wt = expf(al - mx) * inv;
        const float* hp = hs + (size_t)s * H;
        a0 += wt * hp[lane];       a1 += wt * hp[lane + 32];
        a2 += wt * hp[lane + 64];  a3 += wt * hp[lane + 96];
    }
    a0 += bias[lane];      a1 += bias[lane + 32];
    a2 += bias[lane + 64]; a3 += bias[lane + 96];
    if (do_relu) {
        a0 = fmaxf(a0, 0.f); a1 = fmaxf(a1, 0.f);
        a2 = fmaxf(a2, 0.f); a3 = fmaxf(a3, 0.f);
    }
    float* op = out + (size_t)n * H;
    op[lane] = a0; op[lane + 32] = a1; op[lane + 64] = a2; op[lane + 96] = a3;
}

// ---------------- persistent GRU with manual grid barrier --------------------
// Hardened: __nanosleep backoff in the spin to avoid hammering the barrier
// cacheline from 96 blocks (suspected cause of harness timeout / container kill).
__device__ __forceinline__ void grid_barrier() {
    __syncthreads();
    if (threadIdx.x == 0) {
        unsigned gen = *(volatile unsigned*)&d_bar_gen;
        __threadfence();
        if (atomicAdd(&d_bar_cnt, 1u) == (unsigned)(GRU_BLOCKS - 1)) {
            d_bar_cnt = 0u;
            __threadfence();
            atomicAdd(&d_bar_gen, 1u);
        } else {
            while (*(volatile unsigned*)&d_bar_gen == gen) { __nanosleep(64); }
        }
        __threadfence();
    }
    __syncthreads();
}

__global__ void __launch_bounds__(GRU_THREADS, 1)
k_gru(const float* __restrict__ Wh, const float* __restrict__ bh) {
    __shared__ float shW[32 * 256];   // block's 32 columns of Wh, k-major
    __shared__ float shh[16 * 256];   // block's 16 rows of h
    const int tid = threadIdx.x, lane = tid & 31, wrp = tid >> 5;
    const int cg = blockIdx.x % 24, rg = blockIdx.x / 24;
    const int c = cg * 32 + lane;
    for (int i = tid; i < 32 * 256; i += GRU_THREADS) {
        int k = i >> 5, cl = i & 31;
        shW[i] = Wh[k * G3 + cg * 32 + cl];
    }
    const float bh0 = bh[c];
    const int rbase = rg * 16;
    const int rl = wrp * 4;
    __syncthreads();

    for (int t = 0; t < TT; ++t) {
        // stage h rows [rbase, rbase+16)
        const float4* hsrc = (const float4*)(d_hbuf + (rbase << 8));
        float4* hdst = (float4*)shh;
        for (int i = tid; i < 1024; i += GRU_THREADS) hdst[i] = __ldcg(&hsrc[i]);
        __syncthreads();

        // phase A: gh[r, c] = h[r,:] . Wh[:, c]
        float a0 = 0.f, a1 = 0.f, a2 = 0.f, a3 = 0.f;
        const float* h0 = shh + ((rl + 0) << 8);
        const float* h1p = shh + ((rl + 1) << 8);
        const float* h2p = shh + ((rl + 2) << 8);
        const float* h3p = shh + ((rl + 3) << 8);
#pragma unroll 8
        for (int k = 0; k < 256; k += 4) {
            float w0 = shW[(k + 0) * 32 + lane];
            float w1 = shW[(k + 1) * 32 + lane];
            float w2 = shW[(k + 2) * 32 + lane];
            float w3 = shW[(k + 3) * 32 + lane];
            float4 x0 = *(const float4*)(h0 + k);
            float4 x1 = *(const float4*)(h1p + k);
            float4 x2 = *(const float4*)(h2p + k);
            float4 x3 = *(const float4*)(h3p + k);
            a0 += w0 * x0.x + w1 * x0.y + w2 * x0.z + w3 * x0.w;
            a1 += w0 * x1.x + w1 * x1.y + w2 * x1.z + w3 * x1.w;
            a2 += w0 * x2.x + w1 * x2.y + w2 * x2.z + w3 * x2.w;
            a3 += w0 * x3.x + w1 * x3.y + w2 * x3.z + w3 * x3.w;
        }
        d_gh[(rbase + rl + 0) * G3 + c] = a0 + bh0;
        d_gh[(rbase + rl + 1) * G3 + c] = a1 + bh0;
        d_gh[(rbase + rl + 2) * G3 + c] = a2 + bh0;
        d_gh[(rbase + rl + 3) * G3 + c] = a3 + bh0;
        grid_barrier();

        // phase B: gate nonlinearity + state update
        for (int i = blockIdx.x * GRU_THREADS + tid; i < BB * RH; i += GRU_BLOCKS * GRU_THREADS) {
            int b = i >> 8, k = i & 255;
            const float* gp = d_gh + b * G3;
            float hr = __ldcg(gp + k);
            float hz = __ldcg(gp + 256 + k);
            float hn = __ldcg(gp + 512 + k);
            const float* xp = d_xg + (size_t)(b * TT + t) * G3;
            float xr = xp[k], xz = xp[256 + k], xn = xp[512 + k];
            float hprev = __ldcg(&d_hbuf[i]);
            float r  = 1.f / (1.f + expf(-(xr + hr)));
            float z  = 1.f / (1.f + expf(-(xz + hz)));
            float nn = tanhf(xn + r * hn);
            float hnew = (1.f - z) * nn + z * hprev;
            d_hbuf[i] = hnew;
            d_hseq[(size_t)(b * TT + t) * RH + k] = hnew;
        }
        grid_barrier();
    }
}

// ---------------- masked attention pooling + MLP head ------------------------
__global__ void k_att(const int* __restrict__ lengths, const float* __restrict__ w_att,
                      const float* __restrict__ b_att, const float* __restrict__ fc1w,
                      const float* __restrict__ fc1b, const float* __restrict__ fc2w,
                      const float* __restrict__ fc2b, float* __restrict__ out) {
    __shared__ float sc[TT];
    __shared__ float red[8];
    __shared__ float ctx[RH];
    __shared__ float z1[H];
    int b = blockIdx.x, tid = threadIdx.x, lane = tid & 31, wrp = tid >> 5;
    const float* hs = d_hseq + (size_t)b * TT * RH;

    for (int t = wrp; t < TT; t += 8) {
        float p = 0.f;
        const float* hp = hs + t * RH;
        for (int k = lane; k < RH; k += 32) p += hp[k] * w_att[k];
        for (int o = 16; o; o >>= 1) p += __shfl_xor_sync(0xffffffffu, p, o);
        if (lane == 0) sc[t] = p + b_att[0];
    }
    __syncthreads();
    int L = lengths[b];
    float m = -1e30f;
    for (int t = tid; t < L; t += 256) m = fmaxf(m, sc[t]);
    for (int o = 16; o; o >>= 1) m = fmaxf(m, __shfl_xor_sync(0xffffffffu, m, o));
    if (lane == 0) red[wrp] = m;
    __syncthreads();
    if (tid == 0) {
        float mm = red[0];
        for (int i = 1; i < 8; ++i) mm = fmaxf(mm, red[i]);
        red[0] = mm;
    }
    __syncthreads();
    m = red[0];
    __syncthreads();
    float s = 0.f;
    for (int t = tid; t < TT; t += 256) {
        if (t < L) { float e = expf(sc[t] - m); sc[t] = e; s += e; }
        else sc[t] = 0.f;
    }
    for (int o = 16; o; o >>= 1) s += __shfl_xor_sync(0xffffffffu, s, o);
    if (lane == 0) red[wrp] = s;
    __syncthreads();
    if (tid == 0) {
        float ds = 0.f;
        for (int i = 0; i < 8; ++i) ds += red[i];
        red[0] = ds;
    }
    __syncthreads();
    float inv = 1.f / red[0];

    float cacc = 0.f;
    for (int t = 0; t < L; ++t) cacc += sc[t] * hs[t * RH + tid];
    ctx[tid] = cacc * inv;
    __syncthreads();

    if (tid < H) {
        float a = fc1b[tid];
        for (int k = 0; k < RH; ++k) a += ctx[k] * fc1w[k * H + tid];
        z1[tid] = fmaxf(a, 0.f);
    }
    __syncthreads();
    float p = (tid < H) ? z1[tid] * fc2w[tid] : 0.f;
    for (int o = 16; o; o >>= 1) p += __shfl_xor_sync(0xffffffffu, p, o);
    if (lane == 0) red[wrp] = p;
    __syncthreads();
    if (tid == 0) {
        float t2 = 0.f;
        for (int i = 0; i < 8; ++i) t2 += red[i];
        out[b] = t2 + fc2b[0];
    }
}

// ---------------- launch ------------------------------------------------------
extern "C" void kernel_launch(void* const* d_in, const int* in_sizes, int n_in,
                              void* d_out, int out_size) {
    const float* x     = (const float*)d_in[0];
    const int*   ei    = (const int*)d_in[1];
    const int*   lens  = (const int*)d_in[2];
    const float* Wsrc1 = (const float*)d_in[3];
    const float* Wdst1 = (const float*)d_in[4];
    const float* asrc1 = (const float*)d_in[5];
    const float* adst1 = (const float*)d_in[6];
    const float* b1    = (const float*)d_in[7];
    const float* Wsrc2 = (const float*)d_in[8];
    const float* Wdst2 = (const float*)d_in[9];
    const float* asrc2 = (const float*)d_in[10];
    const float* adst2 = (const float*)d_in[11];
    const float* b2    = (const float*)d_in[12];
    const float* Wi    = (const float*)d_in[13];
    const float* Wh    = (const float*)d_in[14];
    const float* bi    = (const float*)d_in[15];
    const float* bh    = (const float*)d_in[16];
    const float* watt  = (const float*)d_in[17];
    const float* batt  = (const float*)d_in[18];
    const float* fc1w  = (const float*)d_in[19];
    const float* fc1b  = (const float*)d_in[20];
    const float* fc2w  = (const float*)d_in[21];
    const float* fc2b  = (const float*)d_in[22];
    float* out = (float*)d_out;

    const int* srcp = ei;
    const int* dstp = ei + EE;

    float *p_hs1, *p_h1, *p_hs2, *p_h2, *p_ss1, *p_sd1, *p_ss2, *p_sd2, *p_v1, *p_v2, *p_xg;
    cudaGetSymbolAddress((void**)&p_hs1, d_hs1);
    cudaGetSymbolAddress((void**)&p_h1,  d_h1);
    cudaGetSymbolAddress((void**)&p_hs2, d_hs2);
    cudaGetSymbolAddress((void**)&p_h2,  d_h2);
    cudaGetSymbolAddress((void**)&p_ss1, d_ss1);
    cudaGetSymbolAddress((void**)&p_sd1, d_sd1);
    cudaGetSymbolAddress((void**)&p_ss2, d_ss2);
    cudaGetSymbolAddress((void**)&p_sd2, d_sd2);
    cudaGetSymbolAddress((void**)&p_v1,  d_v1);
    cudaGetSymbolAddress((void**)&p_v2,  d_v2);
    cudaGetSymbolAddress((void**)&p_xg,  d_xg);

    k_init<<<NN / 256, 256>>>();
    k_count<<<EE / 256, 256>>>(dstp);
    k_scan<<<1, 1024>>>();
    k_scatter<<<EE / 256, 256>>>(srcp, dstp);
    k_vdst<<<2, 256>>>(Wdst1, adst1, Wdst2, adst2);

    // layer 1
    k_gemm<<<dim3(H / 64, NN / 64), 256>>>(x, nullptr, 0, DD, H, Wsrc1, nullptr, p_hs1);
    k_scores<<<NN / 8, 256>>>(p_hs1, H, asrc1, x, DD, p_v1, p_ss1, p_sd1);
    k_aggregate<<<NN / 8, 256>>>(p_ss1, p_sd1, p_hs1, b1, p_h1, 1);

    // layer 2
    k_gemm<<<dim3(H / 64, NN / 64), 256>>>(p_h1, nullptr, 0, H, H, Wsrc2, nullptr, p_hs2);
    k_scores<<<NN / 8, 256>>>(p_hs2, H, asrc2, p_h1, H, p_v2, p_ss2, p_sd2);
    k_aggregate<<<NN / 8, 256>>>(p_ss2, p_sd2, p_hs2, b2, p_h2, 0);

    // GRU input gates: xg = concat(h1,h2) @ Wi + bi
    k_gemm<<<dim3(G3 / 64, NN / 64), 256>>>(p_h1, p_h2, H, DD, G3, Wi, bi, p_xg);

    // GRU recurrence
    k_gru<<<GRU_BLOCKS, GRU_THREADS>>>(Wh, bh);

    // attention + MLP head
    k_att<<<BB, 256>>>(lens, watt, batt, fc1w, fc1b, fc2w, fc2b, out);

    (void)in_sizes; (void)n_in; (void)out_size;
}

// round 13
// speedup vs baseline: 1.5524x; 1.5524x over previous
#include <cuda_runtime.h>
#include <math.h>

#define NN 32768
#define EE 524288
#define BB 64
#define TT 512
#define H  128
#define DD 256
#define RH 256
#define G3 768
#define GRU_BLOCKS 128
#define GRU_THREADS 128
#define GRU_SMEM ((256 * 32 * 4 + 4 * 256) * 4)   // Wh slice padded + 4 h rows

// ---------------- scratch (static device globals; no dynamic alloc) ----------
__device__ __align__(128) float d_hs1[NN * H];
__device__ __align__(128) float d_h1 [NN * H];
__device__ __align__(128) float d_hs2[NN * H];
__device__ __align__(128) float d_h2 [NN * H];
__device__ float d_ss1[NN], d_sd1[NN], d_ss2[NN], d_sd2[NN];
__device__ float d_v1[DD], d_v2[H];
__device__ __align__(128) float d_xg  [(size_t)NN * G3];   // ~100 MB
__device__ __align__(128) float d_hseq[(size_t)NN * RH];   // 32 MB
__device__ __align__(128) float d_hpp[2][BB * RH];         // ping-pong h
__device__ int d_cnt[NN], d_rowptr[NN + 1], d_cursor[NN], d_esrc[EE];
__device__ unsigned d_bar_cnt = 0;
__device__ unsigned d_bar_gen = 0;

// ---------------- init / CSR build ------------------------------------------
__global__ void k_init() {
    int i = blockIdx.x * blockDim.x + threadIdx.x;
    if (i < NN) d_cnt[i] = 0;
    if (i < BB * RH) d_hpp[0][i] = 0.f;
}

__global__ void k_count(const int* __restrict__ dst) {
    int e = blockIdx.x * blockDim.x + threadIdx.x;
    if (e < EE) atomicAdd(&d_cnt[dst[e]], 1);
}

__global__ void k_scan() {
    __shared__ int part[1024];
    int tid = threadIdx.x;
    int base = tid * 32;
    int c[32];
    int s = 0;
#pragma unroll
    for (int j = 0; j < 32; ++j) { c[j] = d_cnt[base + j]; s += c[j]; }
    part[tid] = s;
    __syncthreads();
    if (tid == 0) {
        int run = 0;
        for (int i = 0; i < 1024; ++i) { int t = part[i]; part[i] = run; run += t; }
        d_rowptr[NN] = run;
    }
    __syncthreads();
    int off = part[tid];
#pragma unroll
    for (int j = 0; j < 32; ++j) {
        d_rowptr[base + j] = off;
        d_cursor[base + j] = off;
        off += c[j];
    }
}

__global__ void k_scatter(const int* __restrict__ src, const int* __restrict__ dst) {
    int e = blockIdx.x * blockDim.x + threadIdx.x;
    if (e < EE) {
        int p = atomicAdd(&d_cursor[dst[e]], 1);
        d_esrc[p] = src[e];
    }
}

// ---------------- folded dest-score vectors: v = Wdst @ a_dst ----------------
__global__ void k_vdst(const float* __restrict__ W1, const float* __restrict__ a1,
                       const float* __restrict__ W2, const float* __restrict__ a2) {
    int tid = threadIdx.x;
    if (blockIdx.x == 0) {
        if (tid < DD) {
            float s = 0.f;
            for (int j = 0; j < H; ++j) s += W1[tid * H + j] * a1[j];
            d_v1[tid] = s;
        }
    } else {
        if (tid < H) {
            float s = 0.f;
            for (int j = 0; j < H; ++j) s += W2[tid * H + j] * a2[j];
            d_v2[tid] = s;
        }
    }
}

// ---------------- generic tiled fp32 GEMM: C[M,Nc] = A[M,K]@B[K,Nc] (+bias) --
__global__ void __launch_bounds__(256)
k_gemm(const float* __restrict__ A, const float* __restrict__ A2, int K1,
       int K, int Nc, const float* __restrict__ B, const float* __restrict__ bias,
       float* __restrict__ C) {
    __shared__ float As[16][68];
    __shared__ float Bs[16][64];
    const int bm = blockIdx.y * 64, bn = blockIdx.x * 64;
    const int tid = threadIdx.x;
    const int tc = tid & 15, tr = tid >> 4;
    float acc[4][4] = {};
    for (int k0 = 0; k0 < K; k0 += 16) {
#pragma unroll
        for (int i = tid; i < 64 * 16; i += 256) {
            int m = i >> 4, kk = i & 15;
            int gk = k0 + kk, gm = bm + m;
            float v;
            if (A2) v = (gk < K1) ? A[gm * K1 + gk] : A2[gm * K1 + (gk - K1)];
            else    v = A[(size_t)gm * K + gk];
            As[kk][m] = v;
        }
#pragma unroll
        for (int i = tid; i < 16 * 64; i += 256) {
            int kk = i >> 6, n = i & 63;
            Bs[kk][n] = B[(size_t)(k0 + kk) * Nc + bn + n];
        }
        __syncthreads();
#pragma unroll
        for (int kk = 0; kk < 16; ++kk) {
            float4 av = *(const float4*)&As[kk][tr * 4];
            float4 bv = *(const float4*)&Bs[kk][tc * 4];
            acc[0][0] += av.x * bv.x; acc[0][1] += av.x * bv.y; acc[0][2] += av.x * bv.z; acc[0][3] += av.x * bv.w;
            acc[1][0] += av.y * bv.x; acc[1][1] += av.y * bv.y; acc[1][2] += av.y * bv.z; acc[1][3] += av.y * bv.w;
            acc[2][0] += av.z * bv.x; acc[2][1] += av.z * bv.y; acc[2][2] += av.z * bv.z; acc[2][3] += av.z * bv.w;
            acc[3][0] += av.w * bv.x; acc[3][1] += av.w * bv.y; acc[3][2] += av.w * bv.z; acc[3][3] += av.w * bv.w;
        }
        __syncthreads();
    }
    float b0 = 0, b1 = 0, b2 = 0, b3 = 0;
    if (bias) {
        b0 = bias[bn + tc * 4 + 0]; b1 = bias[bn + tc * 4 + 1];
        b2 = bias[bn + tc * 4 + 2]; b3 = bias[bn + tc * 4 + 3];
    }
#pragma unroll
    for (int i = 0; i < 4; ++i) {
        float4 o;
        o.x = acc[i][0] + b0; o.y = acc[i][1] + b1; o.z = acc[i][2] + b2; o.w = acc[i][3] + b3;
        *(float4*)&C[(size_t)(bm + tr * 4 + i) * Nc + bn + tc * 4] = o;
    }
}

// ---------------- per-node attention scores (two dots per warp) --------------
__global__ void k_scores(const float* __restrict__ A, int KA, const float* __restrict__ av,
                         const float* __restrict__ X, int KX, const float* __restrict__ v,
                         float* __restrict__ ss, float* __restrict__ sd) {
    int lane = threadIdx.x & 31, wrp = threadIdx.x >> 5;
    int n = blockIdx.x * 8 + wrp;
    float p = 0.f;
    for (int k = lane; k < KA; k += 32) p += A[(size_t)n * KA + k] * av[k];
    for (int o = 16; o; o >>= 1) p += __shfl_xor_sync(0xffffffffu, p, o);
    float q = 0.f;
    for (int k = lane; k < KX; k += 32) q += X[(size_t)n * KX + k] * v[k];
    for (int o = 16; o; o >>= 1) q += __shfl_xor_sync(0xffffffffu, q, o);
    if (lane == 0) { ss[n] = p; sd[n] = q; }
}

// ---------------- GAT softmax aggregation (warp per dst node) ----------------
__global__ void k_aggregate(const float* __restrict__ ss, const float* __restrict__ sd,
                            const float* __restrict__ hs, const float* __restrict__ bias,
                            float* __restrict__ out, int do_relu) {
    int lane = threadIdx.x & 31, wrp = threadIdx.x >> 5;
    int n = blockIdx.x * 8 + wrp;
    int beg = d_rowptr[n], end = d_rowptr[n + 1];
    float sdn = sd[n];
    float mx = -1e30f;
    for (int e = beg + lane; e < end; e += 32) {
        float al = ss[d_esrc[e]] + sdn;
        al = al > 0.f ? al : 0.2f * al;
        mx = fmaxf(mx, al);
    }
    for (int o = 16; o; o >>= 1) mx = fmaxf(mx, __shfl_xor_sync(0xffffffffu, mx, o));
    float den = 0.f;
    for (int e = beg + lane; e < end; e += 32) {
        float al = ss[d_esrc[e]] + sdn;
        al = al > 0.f ? al : 0.2f * al;
        den += expf(al - mx);
    }
    for (int o = 16; o; o >>= 1) den += __shfl_xor_sync(0xffffffffu, den, o);
    float inv = 1.f / (den + 1e-16f);
    float a0 = 0.f, a1 = 0.f, a2 = 0.f, a3 = 0.f;
    for (int e = beg; e < end; ++e) {
        int s = d_esrc[e];
        float al = ss[s] + sdn;
        al = al > 0.f ? al : 0.2f * al;
        float wt = expf(al - mx) * inv;
        const float* hp = hs + (size_t)s * H;
        a0 += wt * hp[lane];       a1 += wt * hp[lane + 32];
        a2 += wt * hp[lane + 64];  a3 += wt * hp[lane + 96];
    }
    a0 += bias[lane];      a1 += bias[lane + 32];
    a2 += bias[lane + 64]; a3 += bias[lane + 96];
    if (do_relu) {
        a0 = fmaxf(a0, 0.f); a1 = fmaxf(a1, 0.f);
        a2 = fmaxf(a2, 0.f); a3 = fmaxf(a3, 0.f);
    }
    float* op = out + (size_t)n * H;
    op[lane] = a0; op[lane + 32] = a1; op[lane + 64] = a2; op[lane + 96] = a3;
}

// ---------------- persistent GRU: one grid barrier per step -------------------
__device__ __forceinline__ void grid_barrier() {
    __syncthreads();
    if (threadIdx.x == 0) {
        unsigned gen = *(volatile unsigned*)&d_bar_gen;
        __threadfence();
        if (atomicAdd(&d_bar_cnt, 1u) == (unsigned)(GRU_BLOCKS - 1)) {
            d_bar_cnt = 0u;
            __threadfence();
            atomicAdd(&d_bar_gen, 1u);
        } else {
            int it = 0;
            while (*(volatile unsigned*)&d_bar_gen == gen) {
                if (++it > 64) __nanosleep(128);
            }
        }
        __threadfence();
    }
    __syncthreads();
}

// 128 blocks = 8 col-groups x 16 row-groups. Block: 4 warps = 4 batch rows,
// 32 lanes = 32 hidden cols. Each thread computes all 3 gate dots for its
// (row, col): Wh slice in smem as [k][col][4] (r,z,n,pad -> one LDS.128/k),
// h row broadcast from smem, hprev carried in a register. One barrier/step,
// ping-pong h buffers.
__global__ void __launch_bounds__(GRU_THREADS, 1)
k_gru(const float* __restrict__ Wh, const float* __restrict__ bh) {
    extern __shared__ float smem[];
    float* shW = smem;                 // 256*32*4 floats = 128 KB
    float* shh = smem + 256 * 32 * 4;  // 4*256 floats = 4 KB
    const int tid = threadIdx.x, lane = tid & 31, wrp = tid >> 5;
    const int cg = blockIdx.x & 7;
    const int rg = blockIdx.x >> 3;
    const int c = cg * 32 + lane;      // global hidden column
    const int b = rg * 4 + wrp;        // batch row for this warp

    // stage Wh slice: shW[(k*32+cl)*4+g] = Wh[k][g*RH + cg*32+cl]
    for (int i = tid; i < 256 * 32 * 3; i += GRU_THREADS) {
        int g = i % 3;
        int cl = (i / 3) & 31;
        int k = i / 96;
        shW[(k * 32 + cl) * 4 + g] = Wh[k * G3 + g * RH + cg * 32 + cl];
    }
    const float bhr = bh[c], bhz = bh[RH + c], bhn = bh[2 * RH + c];
    float hprev = 0.f;
    __syncthreads();

    int p = 0;
    for (int t = 0; t < TT; ++t) {
        // prefetch xg for (b, t)
        const float* xp = d_xg + (size_t)(b * TT + t) * G3;
        float xr = __ldcg(xp + c);
        float xz = __ldcg(xp + RH + c);
        float xn = __ldcg(xp + 2 * RH + c);

        // stage this block's 4 h rows (4 KB)
        {
            const float4* hs4 = (const float4*)(d_hpp[p] + (size_t)(rg * 4) * RH);
            float4* sh4 = (float4*)shh;
            sh4[tid]       = __ldcg(&hs4[tid]);
            sh4[tid + 128] = __ldcg(&hs4[tid + 128]);
        }
        __syncthreads();

        float ar = 0.f, az = 0.f, an = 0.f;
        const float* hrow = shh + (wrp << 8);
#pragma unroll 4
        for (int k = 0; k < 256; k += 4) {
            float4 hv = *(const float4*)(hrow + k);
            float4 w0 = *(const float4*)(shW + ((k + 0) * 32 + lane) * 4);
            float4 w1 = *(const float4*)(shW + ((k + 1) * 32 + lane) * 4);
            float4 w2 = *(const float4*)(shW + ((k + 2) * 32 + lane) * 4);
            float4 w3 = *(const float4*)(shW + ((k + 3) * 32 + lane) * 4);
            ar += w0.x * hv.x + w1.x * hv.y + w2.x * hv.z + w3.x * hv.w;
            az += w0.y * hv.x + w1.y * hv.y + w2.y * hv.z + w3.y * hv.w;
            an += w0.z * hv.x + w1.z * hv.y + w2.z * hv.z + w3.z * hv.w;
        }
        float r  = 1.f / (1.f + expf(-(xr + ar + bhr)));
        float z  = 1.f / (1.f + expf(-(xz + az + bhz)));
        float nn = tanhf(xn + r * (an + bhn));
        float hnew = (1.f - z) * nn + z * hprev;
        hprev = hnew;
        d_hpp[p ^ 1][b * RH + c] = hnew;
        d_hseq[(size_t)(b * TT + t) * RH + c] = hnew;
        p ^= 1;
        grid_barrier();
    }
}

// ---------------- masked attention pooling + MLP head ------------------------
__global__ void k_att(const int* __restrict__ lengths, const float* __restrict__ w_att,
                      const float* __restrict__ b_att, const float* __restrict__ fc1w,
                      const float* __restrict__ fc1b, const float* __restrict__ fc2w,
                      const float* __restrict__ fc2b, float* __restrict__ out) {
    __shared__ float sc[TT];
    __shared__ float red[8];
    __shared__ float ctx[RH];
    __shared__ float z1[H];
    int b = blockIdx.x, tid = threadIdx.x, lane = tid & 31, wrp = tid >> 5;
    const float* hs = d_hseq + (size_t)b * TT * RH;

    for (int t = wrp; t < TT; t += 8) {
        float p = 0.f;
        const float* hp = hs + t * RH;
        for (int k = lane; k < RH; k += 32) p += hp[k] * w_att[k];
        for (int o = 16; o; o >>= 1) p += __shfl_xor_sync(0xffffffffu, p, o);
        if (lane == 0) sc[t] = p + b_att[0];
    }
    __syncthreads();
    int L = lengths[b];
    float m = -1e30f;
    for (int t = tid; t < L; t += 256) m = fmaxf(m, sc[t]);
    for (int o = 16; o; o >>= 1) m = fmaxf(m, __shfl_xor_sync(0xffffffffu, m, o));
    if (lane == 0) red[wrp] = m;
    __syncthreads();
    if (tid == 0) {
        float mm = red[0];
        for (int i = 1; i < 8; ++i) mm = fmaxf(mm, red[i]);
        red[0] = mm;
    }
    __syncthreads();
    m = red[0];
    __syncthreads();
    float s = 0.f;
    for (int t = tid; t < TT; t += 256) {
        if (t < L) { float e = expf(sc[t] - m); sc[t] = e; s += e; }
        else sc[t] = 0.f;
    }
    for (int o = 16; o; o >>= 1) s += __shfl_xor_sync(0xffffffffu, s, o);
    if (lane == 0) red[wrp] = s;
    __syncthreads();
    if (tid == 0) {
        float ds = 0.f;
        for (int i = 0; i < 8; ++i) ds += red[i];
        red[0] = ds;
    }
    __syncthreads();
    float inv = 1.f / red[0];

    float cacc = 0.f;
    for (int t = 0; t < L; ++t) cacc += sc[t] * hs[t * RH + tid];
    ctx[tid] = cacc * inv;
    __syncthreads();

    if (tid < H) {
        float a = fc1b[tid];
        for (int k = 0; k < RH; ++k) a += ctx[k] * fc1w[k * H + tid];
        z1[tid] = fmaxf(a, 0.f);
    }
    __syncthreads();
    float p = (tid < H) ? z1[tid] * fc2w[tid] : 0.f;
    for (int o = 16; o; o >>= 1) p += __shfl_xor_sync(0xffffffffu, p, o);
    if (lane == 0) red[wrp] = p;
    __syncthreads();
    if (tid == 0) {
        float t2 = 0.f;
        for (int i = 0; i < 8; ++i) t2 += red[i];
        out[b] = t2 + fc2b[0];
    }
}

// ---------------- launch ------------------------------------------------------
extern "C" void kernel_launch(void* const* d_in, const int* in_sizes, int n_in,
                              void* d_out, int out_size) {
    const float* x     = (const float*)d_in[0];
    const int*   ei    = (const int*)d_in[1];
    const int*   lens  = (const int*)d_in[2];
    const float* Wsrc1 = (const float*)d_in[3];
    const float* Wdst1 = (const float*)d_in[4];
    const float* asrc1 = (const float*)d_in[5];
    const float* adst1 = (const float*)d_in[6];
    const float* b1    = (const float*)d_in[7];
    const float* Wsrc2 = (const float*)d_in[8];
    const float* Wdst2 = (const float*)d_in[9];
    const float* asrc2 = (const float*)d_in[10];
    const float* adst2 = (const float*)d_in[11];
    const float* b2    = (const float*)d_in[12];
    const float* Wi    = (const float*)d_in[13];
    const float* Wh    = (const float*)d_in[14];
    const float* bi    = (const float*)d_in[15];
    const float* bh    = (const float*)d_in[16];
    const float* watt  = (const float*)d_in[17];
    const float* batt  = (const float*)d_in[18];
    const float* fc1w  = (const float*)d_in[19];
    const float* fc1b  = (const float*)d_in[20];
    const float* fc2w  = (const float*)d_in[21];
    const float* fc2b  = (const float*)d_in[22];
    float* out = (float*)d_out;

    const int* srcp = ei;
    const int* dstp = ei + EE;

    float *p_hs1, *p_h1, *p_hs2, *p_h2, *p_ss1, *p_sd1, *p_ss2, *p_sd2, *p_v1, *p_v2, *p_xg;
    cudaGetSymbolAddress((void**)&p_hs1, d_hs1);
    cudaGetSymbolAddress((void**)&p_h1,  d_h1);
    cudaGetSymbolAddress((void**)&p_hs2, d_hs2);
    cudaGetSymbolAddress((void**)&p_h2,  d_h2);
    cudaGetSymbolAddress((void**)&p_ss1, d_ss1);
    cudaGetSymbolAddress((void**)&p_sd1, d_sd1);
    cudaGetSymbolAddress((void**)&p_ss2, d_ss2);
    cudaGetSymbolAddress((void**)&p_sd2, d_sd2);
    cudaGetSymbolAddress((void**)&p_v1,  d_v1);
    cudaGetSymbolAddress((void**)&p_v2,  d_v2);
    cudaGetSymbolAddress((void**)&p_xg,  d_xg);

    cudaFuncSetAttribute(k_gru, cudaFuncAttributeMaxDynamicSharedMemorySize, GRU_SMEM);

    k_init<<<NN / 256, 256>>>();
    k_count<<<EE / 256, 256>>>(dstp);
    k_scan<<<1, 1024>>>();
    k_scatter<<<EE / 256, 256>>>(srcp, dstp);
    k_vdst<<<2, 256>>>(Wdst1, adst1, Wdst2, adst2);

    // layer 1
    k_gemm<<<dim3(H / 64, NN / 64), 256>>>(x, nullptr, 0, DD, H, Wsrc1, nullptr, p_hs1);
    k_scores<<<NN / 8, 256>>>(p_hs1, H, asrc1, x, DD, p_v1, p_ss1, p_sd1);
    k_aggregate<<<NN / 8, 256>>>(p_ss1, p_sd1, p_hs1, b1, p_h1, 1);

    // layer 2
    k_gemm<<<dim3(H / 64, NN / 64), 256>>>(p_h1, nullptr, 0, H, H, Wsrc2, nullptr, p_hs2);
    k_scores<<<NN / 8, 256>>>(p_hs2, H, asrc2, p_h1, H, p_v2, p_ss2, p_sd2);
    k_aggregate<<<NN / 8, 256>>>(p_ss2, p_sd2, p_hs2, b2, p_h2, 0);

    // GRU input gates: xg = concat(h1,h2) @ Wi + bi
    k_gemm<<<dim3(G3 / 64, NN / 64), 256>>>(p_h1, p_h2, H, DD, G3, Wi, bi, p_xg);

    // GRU recurrence (one barrier per step, ping-pong h)
    k_gru<<<GRU_BLOCKS, GRU_THREADS, GRU_SMEM>>>(Wh, bh);

    // attention + MLP head
    k_att<<<BB, 256>>>(lens, watt, batt, fc1w, fc1b, fc2w, fc2b, out);

    (void)in_sizes; (void)n_in; (void)out_size;
}